// round 10
// baseline (speedup 1.0000x reference)
#include <cuda_runtime.h>
#include <cstdint>

namespace {
constexpr int EMBD  = 64;
constexpr int HID   = 128;
constexpr int NN    = 4096;
constexpr int P1    = 2047;
constexpr int STEPS = 4094;
constexpr int CS    = 8;
constexpr int TPB   = 256;
constexpr int SLOT  = 20;           // floats per rank slot (16 h + 2 s + 2 pad)
constexpr int HB    = CS * SLOT;    // 160 floats per buffer
constexpr int NBW   = 22;           // neighbors per thread (warps 2-7: 192 thr)
constexpr int CAP   = 768;          // candidate shortlist capacity

struct SmemB {
    float xe[EMBD];                 // embedding vector
    float hbuf[2][HB];              // double-buffered h + s slots
    float stage[2][16];             // double-buffered bulk-copy staging (h)
    float partial[TPB];
    float gact[64];
    float W_emb_s[EMBD * 2];
    float b_emb_s[EMBD];
    unsigned wm[16];                // [0..7]=lo words per warp, [8..15]=hi
    float2 cand[2][CAP];            // candidate shortlists (double buffered)
    int   cnt[2];
    unsigned long long mb[2];       // transaction mbarriers
};
} // namespace

__device__ float g_xih[(size_t)P1 * 512];      // precomputed x@W_ih (permuted)
__device__ float g_hist[(size_t)STEPS * HID];  // h history (both phases)

// ---------------- PTX helpers ----------------
__device__ __forceinline__ unsigned ctarank() {
    unsigned r; asm("mov.u32 %0, %%cluster_ctarank;" : "=r"(r)); return r;
}
__device__ __forceinline__ void cluster_sync_() {
    asm volatile("barrier.cluster.arrive.aligned;" ::: "memory");
    asm volatile("barrier.cluster.wait.aligned;" ::: "memory");
}
__device__ __forceinline__ unsigned mapa_(unsigned la, unsigned rank) {
    unsigned ra;
    asm("mapa.shared::cluster.u32 %0, %1, %2;" : "=r"(ra) : "r"(la), "r"(rank));
    return ra;
}
__device__ __forceinline__ void mbar_init(unsigned a, unsigned cnt) {
    asm volatile("mbarrier.init.shared.b64 [%0], %1;" :: "r"(a), "r"(cnt) : "memory");
}
__device__ __forceinline__ void mbar_expect(unsigned a, unsigned bytes) {
    asm volatile("mbarrier.arrive.expect_tx.shared.b64 _, [%0], %1;"
                 :: "r"(a), "r"(bytes) : "memory");
}
__device__ __forceinline__ void mbar_wait(unsigned a, unsigned parity) {
    asm volatile(
        "{\n\t.reg .pred P;\n"
        "WL%=:\n\t"
        "mbarrier.try_wait.parity.acquire.cluster.shared::cta.b64 P, [%0], %1, 0x989680;\n\t"
        "@P bra WD%=;\n\t"
        "bra WL%=;\n"
        "WD%=:\n\t}"
        :: "r"(a), "r"(parity) : "memory");
}
__device__ __forceinline__ void st_async_b64(unsigned raddr, unsigned long long v,
                                             unsigned rmbar) {
    asm volatile(
        "st.async.shared::cluster.mbarrier::complete_tx::bytes.b64 [%0], %1, [%2];"
        :: "r"(raddr), "l"(v), "r"(rmbar) : "memory");
}
// one 64B bulk copy: own SMEM staging -> peer SMEM slot, completes on peer mbarrier
__device__ __forceinline__ void bulk_s2s(unsigned dst_cluster, unsigned src_cta,
                                         unsigned bytes, unsigned rmbar) {
    asm volatile(
        "cp.async.bulk.shared::cluster.shared::cta.mbarrier::complete_tx::bytes "
        "[%0], [%1], %2, [%3];"
        :: "r"(dst_cluster), "r"(src_cta), "r"(bytes), "r"(rmbar) : "memory");
}
// f32 reduce over lanes 0..15 via shfl butterfly
__device__ __forceinline__ float reduce16(float v) {
#pragma unroll
    for (int o = 8; o > 0; o >>= 1) v += __shfl_xor_sync(0xFFFFu, v, o);
    return v;
}

// fast activations via MUFU (rel err ~1e-6, far under the 1e-3 threshold)
__device__ __forceinline__ float fsig(float x) {
    return __fdividef(1.0f, 1.0f + __expf(-x));
}
__device__ __forceinline__ float ftanh(float x) {
    return __fdividef(2.0f, 1.0f + __expf(-2.0f * x)) - 1.0f;
}

// occupancy test for one neighbor: exact JAX linspace edge semantics
__device__ __forceinline__ void occ_point(float x, float y, float cx, float cy,
                                          unsigned& lo, unsigned& hi) {
    if (fabsf(x - cx) < 1.6f && fabsf(y - cy) < 1.6f) {
        int ix = -1, iy = -1;
#pragma unroll
        for (int c = 0; c < 6; c++) {
            float ex0 = cx + (0.5f * c - 1.5f);
            float ex1 = cx + (0.5f * c - 1.0f);
            if (x > ex0 && x < ex1) ix = c;
            float ey0 = cy + (0.5f * c - 1.5f);
            float ey1 = cy + (0.5f * c - 1.0f);
            if (y > ey0 && y < ey1) iy = c;
        }
        if (ix >= 0 && iy >= 0) {
            int b = ix * 6 + iy;
            if (b < 32) lo |= 1u << b; else hi |= 1u << (b - 32);
        }
    }
}

// ---------------- Kernel A: phase-1 precompute (fully parallel) ----------------
__global__ void __launch_bounds__(TPB) olstm_pre(
    const float* __restrict__ observed, const float* __restrict__ other,
    const float* __restrict__ W_emb, const float* __restrict__ b_emb,
    const float* __restrict__ W_ih)
{
    __shared__ __align__(16) float x100[100];
    __shared__ unsigned wlo[8], whi[8];
    const int t = blockIdx.x;
    const int tid = threadIdx.x;
    const float px = observed[t * 2],       py = observed[t * 2 + 1];
    const float cx = observed[(t + 1) * 2], cy = observed[(t + 1) * 2 + 1];
    const float dx = cx - px, dy = cy - py;

    const float2* oth2 = reinterpret_cast<const float2*>(other);
    unsigned lo = 0u, hi = 0u;
    for (int i = 0; i < NN / TPB; i++) {
        float2 p = oth2[(size_t)(t + 1) * NN + i * TPB + tid];
        occ_point(p.x, p.y, cx, cy, lo, hi);
    }
    lo = __reduce_or_sync(0xffffffffu, lo);
    hi = __reduce_or_sync(0xffffffffu, hi);
    if ((tid & 31) == 0) { wlo[tid >> 5] = lo; whi[tid >> 5] = hi; }
    if (tid < EMBD) {
        float e = fmaf(dx, W_emb[tid * 2], fmaf(dy, W_emb[tid * 2 + 1], b_emb[tid]));
        x100[tid] = e > 0.0f ? e : 0.0f;
    }
    __syncthreads();
    if (tid >= 64 && tid < 100) {
        int b = tid - 64;
        unsigned fm = (b < 32)
            ? (wlo[0]|wlo[1]|wlo[2]|wlo[3]|wlo[4]|wlo[5]|wlo[6]|wlo[7])
            : (whi[0]|whi[1]|whi[2]|whi[3]|whi[4]|whi[5]|whi[6]|whi[7]);
        x100[tid] = ((fm >> (b & 31)) & 1u) ? 1.0f : 0.0f;
    }
    __syncthreads();

    const float4* xq = reinterpret_cast<const float4*>(x100);
    const float4* w0 = reinterpret_cast<const float4*>(W_ih + (size_t)tid * 100);
    const float4* w1 = reinterpret_cast<const float4*>(W_ih + (size_t)(tid + 256) * 100);
    float a0 = 0.0f, a1 = 0.0f;
#pragma unroll
    for (int i = 0; i < 25; i++) {
        float4 xx = xq[i], wa = w0[i], wb = w1[i];
        a0 = fmaf(wa.x, xx.x, a0); a0 = fmaf(wa.y, xx.y, a0);
        a0 = fmaf(wa.z, xx.z, a0); a0 = fmaf(wa.w, xx.w, a0);
        a1 = fmaf(wb.x, xx.x, a1); a1 = fmaf(wb.y, xx.y, a1);
        a1 = fmaf(wb.z, xx.z, a1); a1 = fmaf(wb.w, xx.w, a1);
    }
    const int r0 = tid, r1 = tid + 256;
    g_xih[(size_t)t * 512 + ((r0 >> 4) & 7) * 64 + (r0 >> 7) * 16 + (r0 & 15)] = a0;
    g_xih[(size_t)t * 512 + ((r1 >> 4) & 7) * 64 + (r1 >> 7) * 16 + (r1 & 15)] = a1;
}

// ---------------- Kernel B helper: gates + bulk h-exchange ----------------
// Caller guarantees tid < 64. StageA on threads 0..63; bar.sync 1,64;
// stageB on threads 0..15 (h computed once), bulk-copied to all 8 ranks.
__device__ __forceinline__ void gates_and_send(SmemB* s, int tid, unsigned rk,
                                               int nxt, unsigned mb_c, unsigned la_h,
                                               unsigned la_stage,
                                               float& cst, float bs_g,
                                               float wo0, float wo1,
                                               bool sendS, float* hist) {
    float gv = bs_g + s->partial[tid] + s->partial[tid + 64]
             + s->partial[tid + 128] + s->partial[tid + 192];
    s->gact[tid] = (tid < 32 || tid >= 48) ? fsig(gv) : ftanh(gv);
    asm volatile("bar.sync 1, 64;" ::: "memory");
    if (tid < 16) {
        const int j = tid;
        float ig = s->gact[j],      fg = s->gact[16 + j];
        float gg = s->gact[32 + j], og = s->gact[48 + j];
        float cN = fmaf(fg, cst, ig * gg);
        cst = cN;
        float hN = og * ftanh(cN);
        s->stage[nxt][j] = hN;
        __syncwarp(0xFFFFu);
        asm volatile("fence.proxy.async.shared::cta;" ::: "memory");
        if (j < 8) {
            unsigned dst = la_h + (unsigned)((nxt * HB + (int)rk * SLOT) * 4);
            bulk_s2s(mapa_(dst, (unsigned)j), la_stage + (unsigned)(nxt * 64),
                     64u, mapa_(mb_c, (unsigned)j));
        }
        if (sendS) {
            float s0 = reduce16(hN * wo0);
            float s1 = reduce16(hN * wo1);
            if (j < 8) {
                unsigned long long pk =
                    (((unsigned long long)__float_as_uint(s1)) << 32)
                    | (unsigned long long)__float_as_uint(s0);
                unsigned sdst = la_h + (unsigned)((nxt * HB + (int)rk * SLOT + 16) * 4);
                st_async_b64(mapa_(sdst, (unsigned)j), pk, mapa_(mb_c, (unsigned)j));
            }
        }
        hist[rk * 16 + j] = hN;                 // off critical path (STG)
    }
}

// ---------------- Kernel B: sequential cluster (8 CTA x 256) ----------------
__global__ void __cluster_dims__(CS, 1, 1) __launch_bounds__(TPB, 1)
olstm_seq(const float* __restrict__ observed, const float* __restrict__ other,
          const float* __restrict__ W_emb, const float* __restrict__ b_emb,
          const float* __restrict__ W_ih,  const float* __restrict__ b_ih,
          const float* __restrict__ W_hh,  const float* __restrict__ b_hh,
          const float* __restrict__ W_out, const float* __restrict__ b_out,
          float* __restrict__ out)
{
    __shared__ __align__(16) SmemB s;
    const int tid = threadIdx.x;
    const unsigned lane = tid & 31;
    const int warp = tid >> 5;
    const unsigned rk = ctarank();
    const int m = tid & 63, part = tid >> 6;
    const int gr = (m >> 4) * HID + (int)rk * 16 + (m & 15);

    // register-resident gate weights: 16 emb cols + 32 h cols + 9 occ cols
    float w[48], wocc[9];
#pragma unroll
    for (int i = 0; i < 16; i++) w[i] = W_ih[(size_t)gr * 100 + part * 16 + i];
#pragma unroll
    for (int i = 0; i < 32; i++) w[16 + i] = W_hh[(size_t)gr * 128 + part * 32 + i];
#pragma unroll
    for (int i = 0; i < 9; i++)  wocc[i] = W_ih[(size_t)gr * 100 + 64 + part * 9 + i];

    // per-thread constants
    float bs_g = 0.0f;                          // gate bias (threads 0..63)
    if (tid < 64) {
        int g2 = (tid >> 4) * HID + (int)rk * 16 + (tid & 15);
        bs_g = b_ih[g2] + b_hh[g2];
    }
    float wo0 = 0.0f, wo1 = 0.0f;               // W_out rows 0,1 cols (threads 0..15)
    if (tid < 16) {
        wo0 = W_out[rk * 16 + tid];
        wo1 = W_out[HID + rk * 16 + tid];
    }
    const float bo0 = b_out[0], bo1 = b_out[1];

    // rigorous one-step drift bound: |n| <= ||W_out row||_2 * sqrt(128) + |b|
    float Rx, Ry;
    {
        float a = 0.0f, b = 0.0f;
        for (int k = (int)lane; k < HID; k += 32) {
            float v0 = W_out[k], v1 = W_out[HID + k];
            a = fmaf(v0, v0, a); b = fmaf(v1, v1, b);
        }
#pragma unroll
        for (int o = 16; o > 0; o >>= 1) {
            a += __shfl_xor_sync(0xffffffffu, a, o);
            b += __shfl_xor_sync(0xffffffffu, b, o);
        }
        Rx = 1.6f + sqrtf(a) * 11.3137086f + fabsf(bo0) + 0.01f;
        Ry = 1.6f + sqrtf(b) * 11.3137086f + fabsf(bo1) + 0.01f;
    }

    for (int i = tid; i < EMBD * 2; i += TPB) s.W_emb_s[i] = W_emb[i];
    if (tid < EMBD) s.b_emb_s[tid] = b_emb[tid];
    for (int i = tid; i < 2 * HB; i += TPB) s.hbuf[0][i] = 0.0f;  // both buffers
    if (tid < 16) s.wm[tid] = 0u;               // warps 0,1 slots stay zero

    const unsigned mb0  = (unsigned)__cvta_generic_to_shared(&s.mb[0]);
    const unsigned mb1  = mb0 + 8;
    const unsigned la_h = (unsigned)__cvta_generic_to_shared(&s.hbuf[0][0]);
    const unsigned la_stage = (unsigned)__cvta_generic_to_shared(&s.stage[0][0]);
    if (tid == 0) { mbar_init(mb0, 1); mbar_init(mb1, 1); mbar_expect(mb0, 512); }
    __syncthreads();
    cluster_sync_();

    const float2* oth2 = reinterpret_cast<const float2*>(other);
    float2 nb[NBW];                             // meaningful on warps 2-7 only
    float cst = 0.0f;                           // cell state (threads 0..15)
    float pcx = 0.0f, pcy = 0.0f, ppx = 0.0f, ppy = 0.0f;  // replicated positions
    float xcur = 0.0f, xnext = 0.0f;
    if (tid < 64) xcur = g_xih[(size_t)rk * 64 + tid];

    // ============ phase 1: precomputed x ============
    for (int t = 0; t < P1; t++) {
        const int cur = t & 1, nxt = cur ^ 1;
        const unsigned mb_c = (t & 1) ? mb1 : mb0;
        const unsigned mb_n = (t & 1) ? mb0 : mb1;
        const bool sendS = (t >= P1 - 2);
        if (tid == 0) mbar_expect(mb_n, (t + 1 >= P1 - 2) ? 576u : 512u);
        if (tid < 64 && t + 1 < P1)
            xnext = g_xih[(size_t)(t + 1) * 512 + (size_t)rk * 64 + tid];

        const float* hb = s.hbuf[cur];
        const float4* hqA = reinterpret_cast<const float4*>(hb + (2 * part) * SLOT);
        const float4* hqB = reinterpret_cast<const float4*>(hb + (2 * part + 1) * SLOT);
        float a0 = (part == 0) ? xcur : 0.0f, a1 = 0.0f, a2 = 0.0f, a3 = 0.0f;
#pragma unroll
        for (int i = 0; i < 4; i++) {
            float4 hh = hqA[i];
            a0 = fmaf(w[16 + 4 * i], hh.x, a0); a1 = fmaf(w[17 + 4 * i], hh.y, a1);
            a2 = fmaf(w[18 + 4 * i], hh.z, a2); a3 = fmaf(w[19 + 4 * i], hh.w, a3);
        }
#pragma unroll
        for (int i = 0; i < 4; i++) {
            float4 hh = hqB[i];
            a0 = fmaf(w[32 + 4 * i], hh.x, a0); a1 = fmaf(w[33 + 4 * i], hh.y, a1);
            a2 = fmaf(w[34 + 4 * i], hh.z, a2); a3 = fmaf(w[35 + 4 * i], hh.w, a3);
        }
        s.partial[tid] = (a0 + a1) + (a2 + a3);
        if (t == P1 - 1 && tid >= 64) {          // load occ row of step P1 (row P1+1)
#pragma unroll
            for (int i = 0; i < NBW; i++) {
                int idx = i * 192 + (tid - 64);
                nb[i] = (idx < NN) ? oth2[(size_t)(P1 + 1) * NN + idx]
                                   : make_float2(1e30f, 1e30f);
            }
        }
        __syncthreads();
        if (tid < 64)
            gates_and_send(&s, tid, rk, nxt, mb_c, la_h, la_stage, cst, bs_g,
                           wo0, wo1, sendS, g_hist + (size_t)t * HID);
        mbar_wait(mb_c, (t >> 1) & 1);
        if (sendS) {                             // carry positions (all threads)
            float n0 = bo0, n1 = bo1;
            const float* hn = s.hbuf[nxt];
#pragma unroll
            for (int r = 0; r < 8; r++) {
                float2 sv = *reinterpret_cast<const float2*>(hn + r * SLOT + 16);
                n0 += sv.x; n1 += sv.y;
            }
            ppx = pcx; ppy = pcy;
            pcx = observed[(t + 1) * 2]     + n0;
            pcy = observed[(t + 1) * 2 + 1] + n1;
        }
        xcur = xnext;
    }

    // ---- bootstrap shortlist for t = P1 (center pc_P1 exact) ----
    if (tid == 0) { s.cnt[0] = 0; s.cnt[1] = 0; }
    __syncthreads();
    if (tid >= 64) {
#pragma unroll
        for (int i = 0; i < NBW; i++) {
            if (fabsf(nb[i].x - pcx) < Rx && fabsf(nb[i].y - pcy) < Ry) {
                int p = atomicAdd(&s.cnt[0], 1);
                if (p < CAP) s.cand[0][p] = nb[i];
            }
        }
#pragma unroll
        for (int i = 0; i < NBW; i++) {          // prefetch row P1+2
            int idx = i * 192 + (tid - 64);
            nb[i] = (idx < NN) ? oth2[(size_t)(P1 + 2) * NN + idx]
                               : make_float2(1e30f, 1e30f);
        }
    }
    __syncthreads();

    // ======================= phase 2 (feedback) =======================
    for (int t = P1; t < STEPS; t++) {
        const int cur = t & 1, nxt = cur ^ 1;
        const unsigned mb_c = (t & 1) ? mb1 : mb0;
        const unsigned mb_n = (t & 1) ? mb0 : mb1;
        const int bc = (t - P1) & 1;
        if (tid == 0) mbar_expect(mb_n, 576u);

        const float cx = pcx, cy = pcy;
        const float dx = pcx - ppx, dy = pcy - ppy;
        if (tid < 64) {
            float e = fmaf(dx, s.W_emb_s[tid * 2],
                      fmaf(dy, s.W_emb_s[tid * 2 + 1], s.b_emb_s[tid]));
            s.xe[tid] = e > 0.0f ? e : 0.0f;
        } else {
            // consume shortlist -> occupancy masks (warps 2-7)
            unsigned lo = 0u, hi = 0u;
            int n = s.cnt[bc];
            if (n <= CAP) {
                for (int idx = tid - 64; idx < n; idx += 192) {
                    float2 p = s.cand[bc][idx];
                    occ_point(p.x, p.y, cx, cy, lo, hi);
                }
            } else {                             // deterministic fallback: full scan
                for (int i = 0; i < NBW; i++) {
                    int idx = i * 192 + (tid - 64);
                    if (idx < NN) {
                        float2 p = __ldg(&oth2[(size_t)(t + 1) * NN + idx]);
                        occ_point(p.x, p.y, cx, cy, lo, hi);
                    }
                }
            }
            lo = __reduce_or_sync(0xffffffffu, lo);
            hi = __reduce_or_sync(0xffffffffu, hi);
            if (lane == 0) { s.wm[warp] = lo; s.wm[8 + warp] = hi; }
            if (tid == 64) s.cnt[bc ^ 1] = 0;    // reset build counter
        }
        __syncthreads();

        // GEMV: emb (reg weights x SMEM xe) + h + occ (reg weights x bits)
        const float* hb = s.hbuf[cur];
        const float4* hqA = reinterpret_cast<const float4*>(hb + (2 * part) * SLOT);
        const float4* hqB = reinterpret_cast<const float4*>(hb + (2 * part + 1) * SLOT);
        const float4* eq = reinterpret_cast<const float4*>(s.xe + part * 16);
        float a0 = 0.0f, a1 = 0.0f, a2 = 0.0f, a3 = 0.0f;
#pragma unroll
        for (int i = 0; i < 4; i++) {
            float4 xx = eq[i];
            a0 = fmaf(w[4 * i],     xx.x, a0); a1 = fmaf(w[4 * i + 1], xx.y, a1);
            a2 = fmaf(w[4 * i + 2], xx.z, a2); a3 = fmaf(w[4 * i + 3], xx.w, a3);
        }
#pragma unroll
        for (int i = 0; i < 4; i++) {
            float4 hh = hqA[i];
            a0 = fmaf(w[16 + 4 * i], hh.x, a0); a1 = fmaf(w[17 + 4 * i], hh.y, a1);
            a2 = fmaf(w[18 + 4 * i], hh.z, a2); a3 = fmaf(w[19 + 4 * i], hh.w, a3);
        }
#pragma unroll
        for (int i = 0; i < 4; i++) {
            float4 hh = hqB[i];
            a0 = fmaf(w[32 + 4 * i], hh.x, a0); a1 = fmaf(w[33 + 4 * i], hh.y, a1);
            a2 = fmaf(w[34 + 4 * i], hh.z, a2); a3 = fmaf(w[35 + 4 * i], hh.w, a3);
        }
        {
            const uint4* wmv = reinterpret_cast<const uint4*>(s.wm);
            uint4 A = wmv[0], B = wmv[1], C = wmv[2], D = wmv[3];
            unsigned flo = A.x|A.y|A.z|A.w|B.x|B.y|B.z|B.w;
            unsigned fhi = C.x|C.y|C.z|C.w|D.x|D.y|D.z|D.w;
            unsigned long long occm = (((unsigned long long)fhi << 32) | flo) >> (part * 9);
#pragma unroll
            for (int i = 0; i < 9; i++) {
                float xb = ((occm >> i) & 1ull) ? 1.0f : 0.0f;
                a0 = fmaf(wocc[i], xb, a0);
            }
        }
        s.partial[tid] = (a0 + a1) + (a2 + a3);
        __syncthreads();

        if (tid < 64) {
            gates_and_send(&s, tid, rk, nxt, mb_c, la_h, la_stage, cst, bs_g,
                           wo0, wo1, true, g_hist + (size_t)t * HID);
        } else {
            // build shortlist for step t+1 (occ row t+2) vs center pc_t, radius R
#pragma unroll
            for (int i = 0; i < NBW; i++) {
                if (fabsf(nb[i].x - cx) < Rx && fabsf(nb[i].y - cy) < Ry) {
                    int p = atomicAdd(&s.cnt[bc ^ 1], 1);
                    if (p < CAP) s.cand[bc ^ 1][p] = nb[i];
                }
            }
            if (t + 3 < NN) {                    // prefetch row t+3
#pragma unroll
                for (int i = 0; i < NBW; i++) {
                    int idx = i * 192 + (tid - 64);
                    nb[i] = (idx < NN) ? oth2[(size_t)(t + 3) * NN + idx]
                                       : make_float2(1e30f, 1e30f);
                }
            }
            asm volatile("bar.sync 2, 192;" ::: "memory");  // build -> next consume HB
        }
        mbar_wait(mb_c, (t >> 1) & 1);

        // post-wait: n0/n1 from piggybacked partials; positions in registers
        {
            float n0 = bo0, n1 = bo1;
            const float* hn = s.hbuf[nxt];
#pragma unroll
            for (int r = 0; r < 8; r++) {
                float2 sv = *reinterpret_cast<const float2*>(hn + r * SLOT + 16);
                n0 += sv.x; n1 += sv.y;
            }
            ppx = pcx; ppy = pcy;
            pcx += n0; pcy += n1;
            if (rk == 0 && tid == 0) {
                out[(size_t)t * 5 + 0] = n0;
                out[(size_t)t * 5 + 1] = n1;
            }
        }
    }
}

// ---------------- Kernel C: output heads (parallel) ----------------
__global__ void __launch_bounds__(160) olstm_head(
    const float* __restrict__ W_out, const float* __restrict__ b_out,
    float* __restrict__ out)
{
    const int t = blockIdx.x;
    const int tid = threadIdx.x;
    const int j = tid >> 5;
    const unsigned lane = tid & 31;
    if (t >= P1 && j < 2) return;
    const float* h = g_hist + (size_t)t * HID;
    float v = 0.0f;
#pragma unroll
    for (int i = 0; i < 4; i++)
        v = fmaf(h[lane + 32 * i], W_out[j * HID + lane + 32 * i], v);
#pragma unroll
    for (int off = 16; off > 0; off >>= 1)
        v += __shfl_down_sync(0xffffffffu, v, off);
    if (lane == 0) out[(size_t)t * 5 + j] = v + b_out[j];
}

extern "C" void kernel_launch(void* const* d_in, const int* in_sizes, int n_in,
                              void* d_out, int out_size) {
    (void)in_sizes; (void)n_in; (void)out_size;
    const float* observed = (const float*)d_in[0];
    const float* other    = (const float*)d_in[1];
    const float* W_emb    = (const float*)d_in[2];
    const float* b_emb    = (const float*)d_in[3];
    const float* W_ih     = (const float*)d_in[4];
    const float* b_ih     = (const float*)d_in[5];
    const float* W_hh     = (const float*)d_in[6];
    const float* b_hh     = (const float*)d_in[7];
    const float* W_out    = (const float*)d_in[8];
    const float* b_out    = (const float*)d_in[9];
    float* out = (float*)d_out;

    olstm_pre<<<P1, TPB>>>(observed, other, W_emb, b_emb, W_ih);
    olstm_seq<<<CS, TPB>>>(observed, other, W_emb, b_emb, W_ih, b_ih,
                           W_hh, b_hh, W_out, b_out, out);
    olstm_head<<<STEPS, 160>>>(W_out, b_out, out);
}

// round 11
// speedup vs baseline: 1.0570x; 1.0570x over previous
#include <cuda_runtime.h>
#include <cstdint>

namespace {
constexpr int EMBD  = 64;
constexpr int HID   = 128;
constexpr int NN    = 4096;
constexpr int P1    = 2047;
constexpr int STEPS = 4094;
constexpr int CS    = 8;
constexpr int TPB   = 256;
constexpr int NBH   = 32;           // neighbors per thread (threads 128..255)
constexpr int CSL   = 8;            // candidate slots per thread
constexpr int SLOT  = 24;           // floats per rank slot in hbuf (16 h + 2 s + pad)
constexpr int HB    = CS * SLOT;    // 192 floats per buffer

struct SmemB {
    float xe[EMBD];                 // embedding vector
    float hbuf[2][HB];              // double-buffered h + s slots
    float partial[TPB];
    float gact[64];
    float W_emb_s[EMBD * 2];
    float b_emb_s[EMBD];
    unsigned wm[16];                // [0..7]=lo words per warp, [8..15]=hi
    float2 cand[2][CSL][128];       // per-thread private candidate slots (16KB)
    unsigned long long mb[2];       // transaction mbarriers
};
} // namespace

__device__ float g_xih[(size_t)P1 * 512];      // precomputed x@W_ih (permuted)
__device__ float g_hist[(size_t)STEPS * HID];  // h history (both phases)

// ---------------- PTX helpers ----------------
__device__ __forceinline__ unsigned ctarank() {
    unsigned r; asm("mov.u32 %0, %%cluster_ctarank;" : "=r"(r)); return r;
}
__device__ __forceinline__ void cluster_sync_() {
    asm volatile("barrier.cluster.arrive.aligned;" ::: "memory");
    asm volatile("barrier.cluster.wait.aligned;" ::: "memory");
}
__device__ __forceinline__ unsigned mapa_(unsigned la, unsigned rank) {
    unsigned ra;
    asm("mapa.shared::cluster.u32 %0, %1, %2;" : "=r"(ra) : "r"(la), "r"(rank));
    return ra;
}
__device__ __forceinline__ void mbar_init(unsigned a, unsigned cnt) {
    asm volatile("mbarrier.init.shared.b64 [%0], %1;" :: "r"(a), "r"(cnt) : "memory");
}
__device__ __forceinline__ void mbar_expect(unsigned a, unsigned bytes) {
    asm volatile("mbarrier.arrive.expect_tx.shared.b64 _, [%0], %1;"
                 :: "r"(a), "r"(bytes) : "memory");
}
__device__ __forceinline__ void mbar_wait(unsigned a, unsigned parity) {
    asm volatile(
        "{\n\t.reg .pred P;\n"
        "WL%=:\n\t"
        "mbarrier.try_wait.parity.acquire.cluster.shared::cta.b64 P, [%0], %1, 0x989680;\n\t"
        "@P bra WD%=;\n\t"
        "bra WL%=;\n"
        "WD%=:\n\t}"
        :: "r"(a), "r"(parity) : "memory");
}
__device__ __forceinline__ void st_async_f32(unsigned raddr, float v, unsigned rmbar) {
    asm volatile(
        "st.async.shared::cluster.mbarrier::complete_tx::bytes.b32 [%0], %1, [%2];"
        :: "r"(raddr), "r"(__float_as_uint(v)), "r"(rmbar) : "memory");
}
__device__ __forceinline__ void st_async_b64(unsigned raddr, unsigned long long v,
                                             unsigned rmbar) {
    asm volatile(
        "st.async.shared::cluster.mbarrier::complete_tx::bytes.b64 [%0], %1, [%2];"
        :: "r"(raddr), "l"(v), "r"(rmbar) : "memory");
}
// f32 reduce over lanes 0..15 via shfl butterfly (redux.f32 not on sm_103)
__device__ __forceinline__ float reduce16(float v) {
#pragma unroll
    for (int o = 8; o > 0; o >>= 1) v += __shfl_xor_sync(0xFFFFu, v, o);
    return v;
}

// fast activations via MUFU (rel err ~1e-6, far under the 1e-3 threshold)
__device__ __forceinline__ float fsig(float x) {
    return __fdividef(1.0f, 1.0f + __expf(-x));
}
__device__ __forceinline__ float ftanh(float x) {
    return __fdividef(2.0f, 1.0f + __expf(-2.0f * x)) - 1.0f;
}

// occupancy test for one neighbor: exact JAX linspace edge semantics
__device__ __forceinline__ void occ_point(float x, float y, float cx, float cy,
                                          unsigned& lo, unsigned& hi) {
    if (fabsf(x - cx) < 1.6f && fabsf(y - cy) < 1.6f) {
        int ix = -1, iy = -1;
#pragma unroll
        for (int c = 0; c < 6; c++) {
            float ex0 = cx + (0.5f * c - 1.5f);
            float ex1 = cx + (0.5f * c - 1.0f);
            if (x > ex0 && x < ex1) ix = c;
            float ey0 = cy + (0.5f * c - 1.5f);
            float ey1 = cy + (0.5f * c - 1.0f);
            if (y > ey0 && y < ey1) iy = c;
        }
        if (ix >= 0 && iy >= 0) {
            int b = ix * 6 + iy;
            if (b < 32) lo |= 1u << b; else hi |= 1u << (b - 32);
        }
    }
}

// ---------------- Kernel A: phase-1 precompute (fully parallel) ----------------
__global__ void __launch_bounds__(TPB) olstm_pre(
    const float* __restrict__ observed, const float* __restrict__ other,
    const float* __restrict__ W_emb, const float* __restrict__ b_emb,
    const float* __restrict__ W_ih)
{
    __shared__ __align__(16) float x100[100];
    __shared__ unsigned wlo[8], whi[8];
    const int t = blockIdx.x;
    const int tid = threadIdx.x;
    const float px = observed[t * 2],       py = observed[t * 2 + 1];
    const float cx = observed[(t + 1) * 2], cy = observed[(t + 1) * 2 + 1];
    const float dx = cx - px, dy = cy - py;

    const float2* oth2 = reinterpret_cast<const float2*>(other);
    unsigned lo = 0u, hi = 0u;
    for (int i = 0; i < NN / TPB; i++) {
        float2 p = oth2[(size_t)(t + 1) * NN + i * TPB + tid];
        occ_point(p.x, p.y, cx, cy, lo, hi);
    }
    lo = __reduce_or_sync(0xffffffffu, lo);
    hi = __reduce_or_sync(0xffffffffu, hi);
    if ((tid & 31) == 0) { wlo[tid >> 5] = lo; whi[tid >> 5] = hi; }
    if (tid < EMBD) {
        float e = fmaf(dx, W_emb[tid * 2], fmaf(dy, W_emb[tid * 2 + 1], b_emb[tid]));
        x100[tid] = e > 0.0f ? e : 0.0f;
    }
    __syncthreads();
    if (tid >= 64 && tid < 100) {
        int b = tid - 64;
        unsigned fm = (b < 32)
            ? (wlo[0]|wlo[1]|wlo[2]|wlo[3]|wlo[4]|wlo[5]|wlo[6]|wlo[7])
            : (whi[0]|whi[1]|whi[2]|whi[3]|whi[4]|whi[5]|whi[6]|whi[7]);
        x100[tid] = ((fm >> (b & 31)) & 1u) ? 1.0f : 0.0f;
    }
    __syncthreads();

    const float4* xq = reinterpret_cast<const float4*>(x100);
    const float4* w0 = reinterpret_cast<const float4*>(W_ih + (size_t)tid * 100);
    const float4* w1 = reinterpret_cast<const float4*>(W_ih + (size_t)(tid + 256) * 100);
    float a0 = 0.0f, a1 = 0.0f;
#pragma unroll
    for (int i = 0; i < 25; i++) {
        float4 xx = xq[i], wa = w0[i], wb = w1[i];
        a0 = fmaf(wa.x, xx.x, a0); a0 = fmaf(wa.y, xx.y, a0);
        a0 = fmaf(wa.z, xx.z, a0); a0 = fmaf(wa.w, xx.w, a0);
        a1 = fmaf(wb.x, xx.x, a1); a1 = fmaf(wb.y, xx.y, a1);
        a1 = fmaf(wb.z, xx.z, a1); a1 = fmaf(wb.w, xx.w, a1);
    }
    const int r0 = tid, r1 = tid + 256;
    g_xih[(size_t)t * 512 + ((r0 >> 4) & 7) * 64 + (r0 >> 7) * 16 + (r0 & 15)] = a0;
    g_xih[(size_t)t * 512 + ((r1 >> 4) & 7) * 64 + (r1 >> 7) * 16 + (r1 & 15)] = a1;
}

// ---------------- Kernel B helper (R9 structure, unchanged) ----------------
__device__ __forceinline__ void gates_and_send(SmemB* s, int tid, unsigned rk,
                                               int nxt, unsigned mb_c, unsigned la_h,
                                               float& cst, float bs_g,
                                               float wo0, float wo1,
                                               bool sendS, float* hist) {
    if (tid < 128) {
        if (tid < 64) {
            float gv = bs_g + s->partial[tid] + s->partial[tid + 64]
                     + s->partial[tid + 128] + s->partial[tid + 192];
            s->gact[tid] = (tid < 32 || tid >= 48) ? fsig(gv) : ftanh(gv);
        }
        asm volatile("bar.sync 1, 128;" ::: "memory");
        const int j = tid & 15, r = tid >> 4;
        float ig = s->gact[j],      fg = s->gact[16 + j];
        float gg = s->gact[32 + j], og = s->gact[48 + j];
        float cN = fmaf(fg, cst, ig * gg);
        cst = cN;
        float hN = og * ftanh(cN);
        unsigned dst = la_h + (unsigned)((nxt * HB + (int)rk * SLOT + j) * 4);
        st_async_f32(mapa_(dst, (unsigned)r), hN, mapa_(mb_c, (unsigned)r));
        if (tid < 16) {
            if (sendS) {
                float s0 = reduce16(hN * wo0);
                float s1 = reduce16(hN * wo1);
                if (tid < 8) {
                    unsigned long long pk =
                        (((unsigned long long)__float_as_uint(s1)) << 32)
                        | (unsigned long long)__float_as_uint(s0);
                    unsigned sdst = la_h + (unsigned)((nxt * HB + (int)rk * SLOT + 16) * 4);
                    st_async_b64(mapa_(sdst, (unsigned)tid), pk,
                                 mapa_(mb_c, (unsigned)tid));
                }
            }
            hist[rk * 16 + tid] = hN;          // off critical path (STG)
        }
    }
}

// ---------------- Kernel B: sequential cluster (8 CTA x 256) ----------------
__global__ void __cluster_dims__(CS, 1, 1) __launch_bounds__(TPB, 1)
olstm_seq(const float* __restrict__ observed, const float* __restrict__ other,
          const float* __restrict__ W_emb, const float* __restrict__ b_emb,
          const float* __restrict__ W_ih,  const float* __restrict__ b_ih,
          const float* __restrict__ W_hh,  const float* __restrict__ b_hh,
          const float* __restrict__ W_out, const float* __restrict__ b_out,
          float* __restrict__ out)
{
    __shared__ __align__(16) SmemB s;
    const int tid = threadIdx.x;
    const unsigned lane = tid & 31;
    const int warp = tid >> 5;
    const unsigned rk = ctarank();
    const int m = tid & 63, part = tid >> 6;
    const int gr = (m >> 4) * HID + (int)rk * 16 + (m & 15);

    // register-resident gate weights: 16 emb cols + 32 h cols + 9 occ cols
    float w[48], wocc[9];
#pragma unroll
    for (int i = 0; i < 16; i++) w[i] = W_ih[(size_t)gr * 100 + part * 16 + i];
#pragma unroll
    for (int i = 0; i < 32; i++) w[16 + i] = W_hh[(size_t)gr * 128 + part * 32 + i];
#pragma unroll
    for (int i = 0; i < 9; i++)  wocc[i] = W_ih[(size_t)gr * 100 + 64 + part * 9 + i];

    // per-thread constants
    float bs_g = 0.0f;                         // gate bias (threads 0..63)
    if (tid < 64) {
        int g2 = (tid >> 4) * HID + (int)rk * 16 + (tid & 15);
        bs_g = b_ih[g2] + b_hh[g2];
    }
    float wo0 = 0.0f, wo1 = 0.0f;              // W_out rows 0,1 cols (threads 0..15)
    if (tid < 16) {
        wo0 = W_out[rk * 16 + tid];
        wo1 = W_out[HID + rk * 16 + tid];
    }
    const float bo0 = b_out[0], bo1 = b_out[1];

    // rigorous one-step drift bound: |n| <= ||W_out row||_2 * sqrt(128) + |b|
    float Rx, Ry;
    {
        float a = 0.0f, b = 0.0f;
        for (int k = (int)lane; k < HID; k += 32) {
            float v0 = W_out[k], v1 = W_out[HID + k];
            a = fmaf(v0, v0, a); b = fmaf(v1, v1, b);
        }
#pragma unroll
        for (int o = 16; o > 0; o >>= 1) {
            a += __shfl_xor_sync(0xffffffffu, a, o);
            b += __shfl_xor_sync(0xffffffffu, b, o);
        }
        Rx = 1.6f + sqrtf(a) * 11.3137086f + fabsf(bo0) + 0.01f;
        Ry = 1.6f + sqrtf(b) * 11.3137086f + fabsf(bo1) + 0.01f;
    }

    for (int i = tid; i < EMBD * 2; i += TPB) s.W_emb_s[i] = W_emb[i];
    if (tid < EMBD) s.b_emb_s[tid] = b_emb[tid];
    for (int i = tid; i < 2 * HB; i += TPB) s.hbuf[0][i] = 0.0f;  // both buffers
    if (tid < 16) s.wm[tid] = 0u;              // warps 0-3 slots stay zero forever

    const unsigned mb0  = (unsigned)__cvta_generic_to_shared(&s.mb[0]);
    const unsigned mb1  = mb0 + 8;
    const unsigned la_h = (unsigned)__cvta_generic_to_shared(&s.hbuf[0][0]);
    if (tid == 0) { mbar_init(mb0, 1); mbar_init(mb1, 1); mbar_expect(mb0, 512); }
    __syncthreads();
    cluster_sync_();

    const float2* oth2 = reinterpret_cast<const float2*>(other);
    float2 nb[NBH];                            // meaningful on threads 128..255
    int ccnt = 0;                              // per-thread candidate count
    const int li = tid - 128;                  // shortlist lane (threads 128..255)
    float cst = 0.0f;                          // cell state (threads 0..15)
    float pcx = 0.0f, pcy = 0.0f, ppx = 0.0f, ppy = 0.0f;  // replicated positions
    float xcur = 0.0f, xnext = 0.0f;
    if (tid < 64) xcur = g_xih[(size_t)rk * 64 + tid];

    // ============ phase 1: precomputed x (R9 structure) ============
    for (int t = 0; t < P1; t++) {
        const int cur = t & 1, nxt = cur ^ 1;
        const unsigned mb_c = (t & 1) ? mb1 : mb0;
        const unsigned mb_n = (t & 1) ? mb0 : mb1;
        const bool sendS = (t >= P1 - 2);
        if (tid == 0) mbar_expect(mb_n, (t + 1 >= P1 - 2) ? 576u : 512u);
        if (tid < 64 && t + 1 < P1)
            xnext = g_xih[(size_t)(t + 1) * 512 + (size_t)rk * 64 + tid];

        const float* hb = s.hbuf[cur];
        const float4* hqA = reinterpret_cast<const float4*>(hb + (2 * part) * SLOT);
        const float4* hqB = reinterpret_cast<const float4*>(hb + (2 * part + 1) * SLOT);
        float a0 = (part == 0) ? xcur : 0.0f, a1 = 0.0f, a2 = 0.0f, a3 = 0.0f;
#pragma unroll
        for (int i = 0; i < 4; i++) {
            float4 hh = hqA[i];
            a0 = fmaf(w[16 + 4 * i], hh.x, a0); a1 = fmaf(w[17 + 4 * i], hh.y, a1);
            a2 = fmaf(w[18 + 4 * i], hh.z, a2); a3 = fmaf(w[19 + 4 * i], hh.w, a3);
        }
#pragma unroll
        for (int i = 0; i < 4; i++) {
            float4 hh = hqB[i];
            a0 = fmaf(w[32 + 4 * i], hh.x, a0); a1 = fmaf(w[33 + 4 * i], hh.y, a1);
            a2 = fmaf(w[34 + 4 * i], hh.z, a2); a3 = fmaf(w[35 + 4 * i], hh.w, a3);
        }
        s.partial[tid] = (a0 + a1) + (a2 + a3);
        if (t == P1 - 1 && tid >= 128) {        // load occ row for step P1 (row P1+1)
#pragma unroll
            for (int i = 0; i < NBH; i++)
                nb[i] = oth2[(size_t)(P1 + 1) * NN + i * 128 + li];
        }
        __syncthreads();
        gates_and_send(&s, tid, rk, nxt, mb_c, la_h, cst, bs_g, wo0, wo1,
                       sendS, g_hist + (size_t)t * HID);
        mbar_wait(mb_c, (t >> 1) & 1);
        if (sendS) {                            // carry positions (all threads)
            float n0 = bo0, n1 = bo1;
            const float* hn = s.hbuf[nxt];
#pragma unroll
            for (int r = 0; r < 8; r++) {
                float2 sv = *reinterpret_cast<const float2*>(hn + r * SLOT + 16);
                n0 += sv.x; n1 += sv.y;
            }
            ppx = pcx; ppy = pcy;
            pcx = observed[(t + 1) * 2]     + n0;
            pcy = observed[(t + 1) * 2 + 1] + n1;
        }
        xcur = xnext;
    }

    // ---- bootstrap shortlist for t = P1 (center pc_P1 exact) + prefetch ----
    if (tid >= 128) {
#pragma unroll
        for (int i = 0; i < NBH; i++) {
            if (fabsf(nb[i].x - pcx) < Rx && fabsf(nb[i].y - pcy) < Ry) {
                if (ccnt < CSL) s.cand[0][ccnt][li] = nb[i];
                ccnt++;
            }
        }
#pragma unroll
        for (int i = 0; i < NBH; i++)
            nb[i] = oth2[(size_t)(P1 + 2) * NN + i * 128 + li];
    }

    // ======================= phase 2 (feedback) =======================
    for (int t = P1; t < STEPS; t++) {
        const int cur = t & 1, nxt = cur ^ 1;
        const unsigned mb_c = (t & 1) ? mb1 : mb0;
        const unsigned mb_n = (t & 1) ? mb0 : mb1;
        const int bc = (t - P1) & 1;
        if (tid == 0) mbar_expect(mb_n, 576u);

        const float cx = pcx, cy = pcy;
        const float dx = pcx - ppx, dy = pcy - ppy;
        if (tid < 64) {
            float e = fmaf(dx, s.W_emb_s[tid * 2],
                      fmaf(dy, s.W_emb_s[tid * 2 + 1], s.b_emb_s[tid]));
            s.xe[tid] = e > 0.0f ? e : 0.0f;
        } else if (tid >= 128) {
            // consume per-thread shortlist -> occupancy bits (warps 4-7)
            unsigned lo = 0u, hi = 0u;
            if (ccnt <= CSL) {
#pragma unroll
                for (int k = 0; k < CSL; k++) {
                    if (k < ccnt) {
                        float2 p = s.cand[bc][k][li];
                        occ_point(p.x, p.y, cx, cy, lo, hi);
                    }
                }
            } else {                            // deterministic overflow fallback
                for (int i = 0; i < NBH; i++) {
                    float2 p = __ldg(&oth2[(size_t)(t + 1) * NN + i * 128 + li]);
                    occ_point(p.x, p.y, cx, cy, lo, hi);
                }
            }
            lo = __reduce_or_sync(0xffffffffu, lo);
            hi = __reduce_or_sync(0xffffffffu, hi);
            if (lane == 0) { s.wm[warp] = lo; s.wm[8 + warp] = hi; }
        }
        __syncthreads();

        // GEMV: emb (reg weights x SMEM xe) + h + occ (reg weights x bits)
        const float* hb = s.hbuf[cur];
        const float4* hqA = reinterpret_cast<const float4*>(hb + (2 * part) * SLOT);
        const float4* hqB = reinterpret_cast<const float4*>(hb + (2 * part + 1) * SLOT);
        const float4* eq = reinterpret_cast<const float4*>(s.xe + part * 16);
        float a0 = 0.0f, a1 = 0.0f, a2 = 0.0f, a3 = 0.0f;
#pragma unroll
        for (int i = 0; i < 4; i++) {
            float4 xx = eq[i];
            a0 = fmaf(w[4 * i],     xx.x, a0); a1 = fmaf(w[4 * i + 1], xx.y, a1);
            a2 = fmaf(w[4 * i + 2], xx.z, a2); a3 = fmaf(w[4 * i + 3], xx.w, a3);
        }
#pragma unroll
        for (int i = 0; i < 4; i++) {
            float4 hh = hqA[i];
            a0 = fmaf(w[16 + 4 * i], hh.x, a0); a1 = fmaf(w[17 + 4 * i], hh.y, a1);
            a2 = fmaf(w[18 + 4 * i], hh.z, a2); a3 = fmaf(w[19 + 4 * i], hh.w, a3);
        }
#pragma unroll
        for (int i = 0; i < 4; i++) {
            float4 hh = hqB[i];
            a0 = fmaf(w[32 + 4 * i], hh.x, a0); a1 = fmaf(w[33 + 4 * i], hh.y, a1);
            a2 = fmaf(w[34 + 4 * i], hh.z, a2); a3 = fmaf(w[35 + 4 * i], hh.w, a3);
        }
        {
            const uint4* wmv = reinterpret_cast<const uint4*>(s.wm);
            uint4 A = wmv[0], B = wmv[1], C = wmv[2], D = wmv[3];
            unsigned flo = A.x|A.y|A.z|A.w|B.x|B.y|B.z|B.w;
            unsigned fhi = C.x|C.y|C.z|C.w|D.x|D.y|D.z|D.w;
            unsigned long long occm = (((unsigned long long)fhi << 32) | flo) >> (part * 9);
#pragma unroll
            for (int i = 0; i < 9; i++) {
                float xb = ((occm >> i) & 1ull) ? 1.0f : 0.0f;
                a0 = fmaf(wocc[i], xb, a0);
            }
        }
        s.partial[tid] = (a0 + a1) + (a2 + a3);
        __syncthreads();

        if (tid < 128) {
            gates_and_send(&s, tid, rk, nxt, mb_c, la_h, cst, bs_g, wo0, wo1,
                           true, g_hist + (size_t)t * HID);
        } else {
            // build shortlist for step t+1 (row t+2) vs center pc_t, radius R;
            // private slots, register count -> no atomics, no extra barriers
            ccnt = 0;
            const int nbuf = bc ^ 1;
#pragma unroll
            for (int i = 0; i < NBH; i++) {
                if (fabsf(nb[i].x - cx) < Rx && fabsf(nb[i].y - cy) < Ry) {
                    if (ccnt < CSL) s.cand[nbuf][ccnt][li] = nb[i];
                    ccnt++;
                }
            }
            if (t + 3 < NN) {                   // prefetch row t+3
#pragma unroll
                for (int i = 0; i < NBH; i++)
                    nb[i] = oth2[(size_t)(t + 3) * NN + i * 128 + li];
            }
        }
        mbar_wait(mb_c, (t >> 1) & 1);

        // post-wait: n0/n1 from piggybacked partials; positions in registers
        {
            float n0 = bo0, n1 = bo1;
            const float* hn = s.hbuf[nxt];
#pragma unroll
            for (int r = 0; r < 8; r++) {
                float2 sv = *reinterpret_cast<const float2*>(hn + r * SLOT + 16);
                n0 += sv.x; n1 += sv.y;
            }
            ppx = pcx; ppy = pcy;
            pcx += n0; pcy += n1;
            if (rk == 0 && tid == 0) {
                out[(size_t)t * 5 + 0] = n0;
                out[(size_t)t * 5 + 1] = n1;
            }
        }
    }
}

// ---------------- Kernel C: output heads (parallel) ----------------
__global__ void __launch_bounds__(160) olstm_head(
    const float* __restrict__ W_out, const float* __restrict__ b_out,
    float* __restrict__ out)
{
    const int t = blockIdx.x;
    const int tid = threadIdx.x;
    const int j = tid >> 5;
    const unsigned lane = tid & 31;
    if (t >= P1 && j < 2) return;
    const float* h = g_hist + (size_t)t * HID;
    float v = 0.0f;
#pragma unroll
    for (int i = 0; i < 4; i++)
        v = fmaf(h[lane + 32 * i], W_out[j * HID + lane + 32 * i], v);
#pragma unroll
    for (int off = 16; off > 0; off >>= 1)
        v += __shfl_down_sync(0xffffffffu, v, off);
    if (lane == 0) out[(size_t)t * 5 + j] = v + b_out[j];
}

extern "C" void kernel_launch(void* const* d_in, const int* in_sizes, int n_in,
                              void* d_out, int out_size) {
    (void)in_sizes; (void)n_in; (void)out_size;
    const float* observed = (const float*)d_in[0];
    const float* other    = (const float*)d_in[1];
    const float* W_emb    = (const float*)d_in[2];
    const float* b_emb    = (const float*)d_in[3];
    const float* W_ih     = (const float*)d_in[4];
    const float* b_ih     = (const float*)d_in[5];
    const float* W_hh     = (const float*)d_in[6];
    const float* b_hh     = (const float*)d_in[7];
    const float* W_out    = (const float*)d_in[8];
    const float* b_out    = (const float*)d_in[9];
    float* out = (float*)d_out;

    olstm_pre<<<P1, TPB>>>(observed, other, W_emb, b_emb, W_ih);
    olstm_seq<<<CS, TPB>>>(observed, other, W_emb, b_emb, W_ih, b_ih,
                           W_hh, b_hh, W_out, b_out, out);
    olstm_head<<<STEPS, 160>>>(W_out, b_out, out);
}

// round 12
// speedup vs baseline: 1.2127x; 1.1472x over previous
#include <cuda_runtime.h>
#include <cstdint>

namespace {
constexpr int EMBD  = 64;
constexpr int HID   = 128;
constexpr int NN    = 4096;
constexpr int P1    = 2047;
constexpr int STEPS = 4094;
constexpr int CS    = 8;
constexpr int TPB   = 256;
constexpr int NBT   = NN / TPB;     // 16 neighbors per thread (ALL threads, as R9)
constexpr int CSL   = 6;            // private candidate slots per thread
constexpr int SLOT  = 24;           // floats per rank slot in hbuf (16 h + 2 s + pad)
constexpr int HB    = CS * SLOT;    // 192 floats per buffer

struct SmemB {
    float xe[EMBD];                 // embedding vector
    float hbuf[2][HB];              // double-buffered h + s slots
    float partial[TPB];
    float gact[64];
    float W_emb_s[EMBD * 2];
    float b_emb_s[EMBD];
    unsigned wm[16];                // [0..7]=lo words per warp, [8..15]=hi
    float2 cand[2][CSL][TPB];       // per-thread private candidate slots (24KB)
    unsigned long long mb[2];       // transaction mbarriers
};
} // namespace

__device__ float g_xih[(size_t)P1 * 512];      // precomputed x@W_ih (permuted)
__device__ float g_hist[(size_t)STEPS * HID];  // h history (both phases)

// ---------------- PTX helpers ----------------
__device__ __forceinline__ unsigned ctarank() {
    unsigned r; asm("mov.u32 %0, %%cluster_ctarank;" : "=r"(r)); return r;
}
__device__ __forceinline__ void cluster_sync_() {
    asm volatile("barrier.cluster.arrive.aligned;" ::: "memory");
    asm volatile("barrier.cluster.wait.aligned;" ::: "memory");
}
__device__ __forceinline__ unsigned mapa_(unsigned la, unsigned rank) {
    unsigned ra;
    asm("mapa.shared::cluster.u32 %0, %1, %2;" : "=r"(ra) : "r"(la), "r"(rank));
    return ra;
}
__device__ __forceinline__ void mbar_init(unsigned a, unsigned cnt) {
    asm volatile("mbarrier.init.shared.b64 [%0], %1;" :: "r"(a), "r"(cnt) : "memory");
}
__device__ __forceinline__ void mbar_expect(unsigned a, unsigned bytes) {
    asm volatile("mbarrier.arrive.expect_tx.shared.b64 _, [%0], %1;"
                 :: "r"(a), "r"(bytes) : "memory");
}
__device__ __forceinline__ void mbar_wait(unsigned a, unsigned parity) {
    asm volatile(
        "{\n\t.reg .pred P;\n"
        "WL%=:\n\t"
        "mbarrier.try_wait.parity.acquire.cluster.shared::cta.b64 P, [%0], %1, 0x989680;\n\t"
        "@P bra WD%=;\n\t"
        "bra WL%=;\n"
        "WD%=:\n\t}"
        :: "r"(a), "r"(parity) : "memory");
}
__device__ __forceinline__ void st_async_f32(unsigned raddr, float v, unsigned rmbar) {
    asm volatile(
        "st.async.shared::cluster.mbarrier::complete_tx::bytes.b32 [%0], %1, [%2];"
        :: "r"(raddr), "r"(__float_as_uint(v)), "r"(rmbar) : "memory");
}
__device__ __forceinline__ void st_async_b64(unsigned raddr, unsigned long long v,
                                             unsigned rmbar) {
    asm volatile(
        "st.async.shared::cluster.mbarrier::complete_tx::bytes.b64 [%0], %1, [%2];"
        :: "r"(raddr), "l"(v), "r"(rmbar) : "memory");
}
// f32 reduce over lanes 0..15 via shfl butterfly (redux.f32 not on sm_103)
__device__ __forceinline__ float reduce16(float v) {
#pragma unroll
    for (int o = 8; o > 0; o >>= 1) v += __shfl_xor_sync(0xFFFFu, v, o);
    return v;
}

// fast activations via MUFU (rel err ~1e-6, far under the 1e-3 threshold)
__device__ __forceinline__ float fsig(float x) {
    return __fdividef(1.0f, 1.0f + __expf(-x));
}
__device__ __forceinline__ float ftanh(float x) {
    return __fdividef(2.0f, 1.0f + __expf(-2.0f * x)) - 1.0f;
}

// occupancy test for one neighbor: exact JAX linspace edge semantics
__device__ __forceinline__ void occ_point(float x, float y, float cx, float cy,
                                          unsigned& lo, unsigned& hi) {
    if (fabsf(x - cx) < 1.6f && fabsf(y - cy) < 1.6f) {
        int ix = -1, iy = -1;
#pragma unroll
        for (int c = 0; c < 6; c++) {
            float ex0 = cx + (0.5f * c - 1.5f);
            float ex1 = cx + (0.5f * c - 1.0f);
            if (x > ex0 && x < ex1) ix = c;
            float ey0 = cy + (0.5f * c - 1.5f);
            float ey1 = cy + (0.5f * c - 1.0f);
            if (y > ey0 && y < ey1) iy = c;
        }
        if (ix >= 0 && iy >= 0) {
            int b = ix * 6 + iy;
            if (b < 32) lo |= 1u << b; else hi |= 1u << (b - 32);
        }
    }
}

// ---------------- Kernel A: phase-1 precompute (fully parallel) ----------------
__global__ void __launch_bounds__(TPB) olstm_pre(
    const float* __restrict__ observed, const float* __restrict__ other,
    const float* __restrict__ W_emb, const float* __restrict__ b_emb,
    const float* __restrict__ W_ih)
{
    __shared__ __align__(16) float x100[100];
    __shared__ unsigned wlo[8], whi[8];
    const int t = blockIdx.x;
    const int tid = threadIdx.x;
    const float px = observed[t * 2],       py = observed[t * 2 + 1];
    const float cx = observed[(t + 1) * 2], cy = observed[(t + 1) * 2 + 1];
    const float dx = cx - px, dy = cy - py;

    const float2* oth2 = reinterpret_cast<const float2*>(other);
    unsigned lo = 0u, hi = 0u;
    for (int i = 0; i < NBT; i++) {
        float2 p = oth2[(size_t)(t + 1) * NN + i * TPB + tid];
        occ_point(p.x, p.y, cx, cy, lo, hi);
    }
    lo = __reduce_or_sync(0xffffffffu, lo);
    hi = __reduce_or_sync(0xffffffffu, hi);
    if ((tid & 31) == 0) { wlo[tid >> 5] = lo; whi[tid >> 5] = hi; }
    if (tid < EMBD) {
        float e = fmaf(dx, W_emb[tid * 2], fmaf(dy, W_emb[tid * 2 + 1], b_emb[tid]));
        x100[tid] = e > 0.0f ? e : 0.0f;
    }
    __syncthreads();
    if (tid >= 64 && tid < 100) {
        int b = tid - 64;
        unsigned fm = (b < 32)
            ? (wlo[0]|wlo[1]|wlo[2]|wlo[3]|wlo[4]|wlo[5]|wlo[6]|wlo[7])
            : (whi[0]|whi[1]|whi[2]|whi[3]|whi[4]|whi[5]|whi[6]|whi[7]);
        x100[tid] = ((fm >> (b & 31)) & 1u) ? 1.0f : 0.0f;
    }
    __syncthreads();

    const float4* xq = reinterpret_cast<const float4*>(x100);
    const float4* w0 = reinterpret_cast<const float4*>(W_ih + (size_t)tid * 100);
    const float4* w1 = reinterpret_cast<const float4*>(W_ih + (size_t)(tid + 256) * 100);
    float a0 = 0.0f, a1 = 0.0f;
#pragma unroll
    for (int i = 0; i < 25; i++) {
        float4 xx = xq[i], wa = w0[i], wb = w1[i];
        a0 = fmaf(wa.x, xx.x, a0); a0 = fmaf(wa.y, xx.y, a0);
        a0 = fmaf(wa.z, xx.z, a0); a0 = fmaf(wa.w, xx.w, a0);
        a1 = fmaf(wb.x, xx.x, a1); a1 = fmaf(wb.y, xx.y, a1);
        a1 = fmaf(wb.z, xx.z, a1); a1 = fmaf(wb.w, xx.w, a1);
    }
    const int r0 = tid, r1 = tid + 256;
    g_xih[(size_t)t * 512 + ((r0 >> 4) & 7) * 64 + (r0 >> 7) * 16 + (r0 & 15)] = a0;
    g_xih[(size_t)t * 512 + ((r1 >> 4) & 7) * 64 + (r1 >> 7) * 16 + (r1 & 15)] = a1;
}

// ---------------- Kernel B helper (R9 structure, unchanged) ----------------
__device__ __forceinline__ void gates_and_send(SmemB* s, int tid, unsigned rk,
                                               int nxt, unsigned mb_c, unsigned la_h,
                                               float& cst, float bs_g,
                                               float wo0, float wo1,
                                               bool sendS, float* hist) {
    if (tid < 128) {
        if (tid < 64) {
            float gv = bs_g + s->partial[tid] + s->partial[tid + 64]
                     + s->partial[tid + 128] + s->partial[tid + 192];
            s->gact[tid] = (tid < 32 || tid >= 48) ? fsig(gv) : ftanh(gv);
        }
        asm volatile("bar.sync 1, 128;" ::: "memory");
        const int j = tid & 15, r = tid >> 4;
        float ig = s->gact[j],      fg = s->gact[16 + j];
        float gg = s->gact[32 + j], og = s->gact[48 + j];
        float cN = fmaf(fg, cst, ig * gg);
        cst = cN;
        float hN = og * ftanh(cN);
        unsigned dst = la_h + (unsigned)((nxt * HB + (int)rk * SLOT + j) * 4);
        st_async_f32(mapa_(dst, (unsigned)r), hN, mapa_(mb_c, (unsigned)r));
        if (tid < 16) {
            if (sendS) {
                float s0 = reduce16(hN * wo0);
                float s1 = reduce16(hN * wo1);
                if (tid < 8) {
                    unsigned long long pk =
                        (((unsigned long long)__float_as_uint(s1)) << 32)
                        | (unsigned long long)__float_as_uint(s0);
                    unsigned sdst = la_h + (unsigned)((nxt * HB + (int)rk * SLOT + 16) * 4);
                    st_async_b64(mapa_(sdst, (unsigned)tid), pk,
                                 mapa_(mb_c, (unsigned)tid));
                }
            }
            hist[rk * 16 + tid] = hN;          // off critical path (STG)
        }
    }
}

// ---------------- Kernel B: sequential cluster (8 CTA x 256) ----------------
__global__ void __cluster_dims__(CS, 1, 1) __launch_bounds__(TPB, 1)
olstm_seq(const float* __restrict__ observed, const float* __restrict__ other,
          const float* __restrict__ W_emb, const float* __restrict__ b_emb,
          const float* __restrict__ W_ih,  const float* __restrict__ b_ih,
          const float* __restrict__ W_hh,  const float* __restrict__ b_hh,
          const float* __restrict__ W_out, const float* __restrict__ b_out,
          float* __restrict__ out)
{
    __shared__ __align__(16) SmemB s;
    const int tid = threadIdx.x;
    const unsigned lane = tid & 31;
    const int warp = tid >> 5;
    const unsigned rk = ctarank();
    const int m = tid & 63, part = tid >> 6;
    const int gr = (m >> 4) * HID + (int)rk * 16 + (m & 15);

    // register-resident gate weights: 16 emb cols + 32 h cols + 9 occ cols
    float w[48], wocc[9];
#pragma unroll
    for (int i = 0; i < 16; i++) w[i] = W_ih[(size_t)gr * 100 + part * 16 + i];
#pragma unroll
    for (int i = 0; i < 32; i++) w[16 + i] = W_hh[(size_t)gr * 128 + part * 32 + i];
#pragma unroll
    for (int i = 0; i < 9; i++)  wocc[i] = W_ih[(size_t)gr * 100 + 64 + part * 9 + i];

    // per-thread constants
    float bs_g = 0.0f;                         // gate bias (threads 0..63)
    if (tid < 64) {
        int g2 = (tid >> 4) * HID + (int)rk * 16 + (tid & 15);
        bs_g = b_ih[g2] + b_hh[g2];
    }
    float wo0 = 0.0f, wo1 = 0.0f;              // W_out rows 0,1 cols (threads 0..15)
    if (tid < 16) {
        wo0 = W_out[rk * 16 + tid];
        wo1 = W_out[HID + rk * 16 + tid];
    }
    const float bo0 = b_out[0], bo1 = b_out[1];

    // rigorous one-step drift bound: |n| <= ||W_out row||_2 * sqrt(128) + |b|
    float Rx, Ry;
    {
        float a = 0.0f, b = 0.0f;
        for (int k = (int)lane; k < HID; k += 32) {
            float v0 = W_out[k], v1 = W_out[HID + k];
            a = fmaf(v0, v0, a); b = fmaf(v1, v1, b);
        }
#pragma unroll
        for (int o = 16; o > 0; o >>= 1) {
            a += __shfl_xor_sync(0xffffffffu, a, o);
            b += __shfl_xor_sync(0xffffffffu, b, o);
        }
        Rx = 1.6f + sqrtf(a) * 11.3137086f + fabsf(bo0) + 0.01f;
        Ry = 1.6f + sqrtf(b) * 11.3137086f + fabsf(bo1) + 0.01f;
    }

    for (int i = tid; i < EMBD * 2; i += TPB) s.W_emb_s[i] = W_emb[i];
    if (tid < EMBD) s.b_emb_s[tid] = b_emb[tid];
    for (int i = tid; i < 2 * HB; i += TPB) s.hbuf[0][i] = 0.0f;  // both buffers
    if (tid < 16) s.wm[tid] = 0u;

    const unsigned mb0  = (unsigned)__cvta_generic_to_shared(&s.mb[0]);
    const unsigned mb1  = mb0 + 8;
    const unsigned la_h = (unsigned)__cvta_generic_to_shared(&s.hbuf[0][0]);
    if (tid == 0) { mbar_init(mb0, 1); mbar_init(mb1, 1); mbar_expect(mb0, 512); }
    __syncthreads();
    cluster_sync_();

    const float2* oth2 = reinterpret_cast<const float2*>(other);
    float2 nb[NBT];                            // 16 per thread, ALL threads (as R9)
    int ccnt = 0;                              // per-thread shortlist count
    float cst = 0.0f;                          // cell state (threads 0..15)
    float pcx = 0.0f, pcy = 0.0f, ppx = 0.0f, ppy = 0.0f;  // replicated positions
    float xcur = 0.0f, xnext = 0.0f;
    if (tid < 64) xcur = g_xih[(size_t)rk * 64 + tid];

    // ============ phase 1: precomputed x (R9 structure) ============
    for (int t = 0; t < P1; t++) {
        const int cur = t & 1, nxt = cur ^ 1;
        const unsigned mb_c = (t & 1) ? mb1 : mb0;
        const unsigned mb_n = (t & 1) ? mb0 : mb1;
        const bool sendS = (t >= P1 - 2);
        if (tid == 0) mbar_expect(mb_n, (t + 1 >= P1 - 2) ? 576u : 512u);
        if (tid < 64 && t + 1 < P1)
            xnext = g_xih[(size_t)(t + 1) * 512 + (size_t)rk * 64 + tid];

        const float* hb = s.hbuf[cur];
        const float4* hqA = reinterpret_cast<const float4*>(hb + (2 * part) * SLOT);
        const float4* hqB = reinterpret_cast<const float4*>(hb + (2 * part + 1) * SLOT);
        float a0 = (part == 0) ? xcur : 0.0f, a1 = 0.0f, a2 = 0.0f, a3 = 0.0f;
#pragma unroll
        for (int i = 0; i < 4; i++) {
            float4 hh = hqA[i];
            a0 = fmaf(w[16 + 4 * i], hh.x, a0); a1 = fmaf(w[17 + 4 * i], hh.y, a1);
            a2 = fmaf(w[18 + 4 * i], hh.z, a2); a3 = fmaf(w[19 + 4 * i], hh.w, a3);
        }
#pragma unroll
        for (int i = 0; i < 4; i++) {
            float4 hh = hqB[i];
            a0 = fmaf(w[32 + 4 * i], hh.x, a0); a1 = fmaf(w[33 + 4 * i], hh.y, a1);
            a2 = fmaf(w[34 + 4 * i], hh.z, a2); a3 = fmaf(w[35 + 4 * i], hh.w, a3);
        }
        s.partial[tid] = (a0 + a1) + (a2 + a3);
        if (t == P1 - 1) {                      // load occ row for step P1 (row P1+1)
#pragma unroll
            for (int i = 0; i < NBT; i++)
                nb[i] = oth2[(size_t)(P1 + 1) * NN + i * TPB + tid];
        }
        __syncthreads();
        gates_and_send(&s, tid, rk, nxt, mb_c, la_h, cst, bs_g, wo0, wo1,
                       sendS, g_hist + (size_t)t * HID);
        mbar_wait(mb_c, (t >> 1) & 1);
        if (sendS) {                            // carry positions (all threads)
            float n0 = bo0, n1 = bo1;
            const float* hn = s.hbuf[nxt];
#pragma unroll
            for (int r = 0; r < 8; r++) {
                float2 sv = *reinterpret_cast<const float2*>(hn + r * SLOT + 16);
                n0 += sv.x; n1 += sv.y;
            }
            ppx = pcx; ppy = pcy;
            pcx = observed[(t + 1) * 2]     + n0;
            pcy = observed[(t + 1) * 2 + 1] + n1;
        }
        xcur = xnext;
    }

    // ---- bootstrap shortlist for t = P1 (center pc_P1) + prefetch row P1+2 ----
    {
#pragma unroll
        for (int i = 0; i < NBT; i++) {
            if (fabsf(nb[i].x - pcx) < Rx && fabsf(nb[i].y - pcy) < Ry) {
                if (ccnt < CSL) s.cand[0][ccnt][tid] = nb[i];
                ccnt++;
            }
        }
#pragma unroll
        for (int i = 0; i < NBT; i++)
            nb[i] = oth2[(size_t)(P1 + 2) * NN + i * TPB + tid];
    }

    // ======================= phase 2 (feedback) =======================
    for (int t = P1; t < STEPS; t++) {
        const int cur = t & 1, nxt = cur ^ 1;
        const unsigned mb_c = (t & 1) ? mb1 : mb0;
        const unsigned mb_n = (t & 1) ? mb0 : mb1;
        const int bc = (t - P1) & 1;
        if (tid == 0) mbar_expect(mb_n, 576u);

        const float cx = pcx, cy = pcy;
        const float dx = pcx - ppx, dy = pcy - ppy;
        // consume per-thread shortlist -> occupancy bits (all threads)
        unsigned lo = 0u, hi = 0u;
        if (ccnt <= CSL) {
#pragma unroll
            for (int k = 0; k < CSL; k++) {
                if (k < ccnt) {
                    float2 p = s.cand[bc][k][tid];
                    occ_point(p.x, p.y, cx, cy, lo, hi);
                }
            }
        } else {                                // deterministic overflow fallback
            for (int i = 0; i < NBT; i++) {
                float2 p = __ldg(&oth2[(size_t)(t + 1) * NN + i * TPB + tid]);
                occ_point(p.x, p.y, cx, cy, lo, hi);
            }
        }
        lo = __reduce_or_sync(0xffffffffu, lo);
        hi = __reduce_or_sync(0xffffffffu, hi);
        if (lane == 0) { s.wm[warp] = lo; s.wm[8 + warp] = hi; }
        if (tid < 64) {
            float e = fmaf(dx, s.W_emb_s[tid * 2],
                      fmaf(dy, s.W_emb_s[tid * 2 + 1], s.b_emb_s[tid]));
            s.xe[tid] = e > 0.0f ? e : 0.0f;
        }
        __syncthreads();

        // GEMV: emb (reg weights x SMEM xe) + h + occ (reg weights x bits)
        const float* hb = s.hbuf[cur];
        const float4* hqA = reinterpret_cast<const float4*>(hb + (2 * part) * SLOT);
        const float4* hqB = reinterpret_cast<const float4*>(hb + (2 * part + 1) * SLOT);
        const float4* eq = reinterpret_cast<const float4*>(s.xe + part * 16);
        float a0 = 0.0f, a1 = 0.0f, a2 = 0.0f, a3 = 0.0f;
#pragma unroll
        for (int i = 0; i < 4; i++) {
            float4 xx = eq[i];
            a0 = fmaf(w[4 * i],     xx.x, a0); a1 = fmaf(w[4 * i + 1], xx.y, a1);
            a2 = fmaf(w[4 * i + 2], xx.z, a2); a3 = fmaf(w[4 * i + 3], xx.w, a3);
        }
#pragma unroll
        for (int i = 0; i < 4; i++) {
            float4 hh = hqA[i];
            a0 = fmaf(w[16 + 4 * i], hh.x, a0); a1 = fmaf(w[17 + 4 * i], hh.y, a1);
            a2 = fmaf(w[18 + 4 * i], hh.z, a2); a3 = fmaf(w[19 + 4 * i], hh.w, a3);
        }
#pragma unroll
        for (int i = 0; i < 4; i++) {
            float4 hh = hqB[i];
            a0 = fmaf(w[32 + 4 * i], hh.x, a0); a1 = fmaf(w[33 + 4 * i], hh.y, a1);
            a2 = fmaf(w[34 + 4 * i], hh.z, a2); a3 = fmaf(w[35 + 4 * i], hh.w, a3);
        }
        {
            const uint4* wmv = reinterpret_cast<const uint4*>(s.wm);
            uint4 A = wmv[0], B = wmv[1], C = wmv[2], D = wmv[3];
            unsigned flo = A.x|A.y|A.z|A.w|B.x|B.y|B.z|B.w;
            unsigned fhi = C.x|C.y|C.z|C.w|D.x|D.y|D.z|D.w;
            unsigned long long occm = (((unsigned long long)fhi << 32) | flo) >> (part * 9);
#pragma unroll
            for (int i = 0; i < 9; i++) {
                float xb = ((occm >> i) & 1ull) ? 1.0f : 0.0f;
                a0 = fmaf(wocc[i], xb, a0);
            }
        }
        s.partial[tid] = (a0 + a1) + (a2 + a3);
        __syncthreads();

        gates_and_send(&s, tid, rk, nxt, mb_c, la_h, cst, bs_g, wo0, wo1,
                       true, g_hist + (size_t)t * HID);

        // build shortlist for step t+1 (row t+2) vs center pc_t, radius R;
        // private slots + register count: no atomics, no barriers (slack window)
        {
            ccnt = 0;
            const int nbuf = bc ^ 1;
#pragma unroll
            for (int i = 0; i < NBT; i++) {
                if (fabsf(nb[i].x - cx) < Rx && fabsf(nb[i].y - cy) < Ry) {
                    if (ccnt < CSL) s.cand[nbuf][ccnt][tid] = nb[i];
                    ccnt++;
                }
            }
            if (t + 2 < STEPS) {                // prefetch row t+3
#pragma unroll
                for (int i = 0; i < NBT; i++)
                    nb[i] = oth2[(size_t)(t + 3) * NN + i * TPB + tid];
            }
        }
        mbar_wait(mb_c, (t >> 1) & 1);

        // post-wait: n0/n1 from piggybacked partials; positions in registers
        {
            float n0 = bo0, n1 = bo1;
            const float* hn = s.hbuf[nxt];
#pragma unroll
            for (int r = 0; r < 8; r++) {
                float2 sv = *reinterpret_cast<const float2*>(hn + r * SLOT + 16);
                n0 += sv.x; n1 += sv.y;
            }
            ppx = pcx; ppy = pcy;
            pcx += n0; pcy += n1;
            if (rk == 0 && tid == 0) {
                out[(size_t)t * 5 + 0] = n0;
                out[(size_t)t * 5 + 1] = n1;
            }
        }
    }
}

// ---------------- Kernel C: output heads (parallel) ----------------
__global__ void __launch_bounds__(160) olstm_head(
    const float* __restrict__ W_out, const float* __restrict__ b_out,
    float* __restrict__ out)
{
    const int t = blockIdx.x;
    const int tid = threadIdx.x;
    const int j = tid >> 5;
    const unsigned lane = tid & 31;
    if (t >= P1 && j < 2) return;
    const float* h = g_hist + (size_t)t * HID;
    float v = 0.0f;
#pragma unroll
    for (int i = 0; i < 4; i++)
        v = fmaf(h[lane + 32 * i], W_out[j * HID + lane + 32 * i], v);
#pragma unroll
    for (int off = 16; off > 0; off >>= 1)
        v += __shfl_down_sync(0xffffffffu, v, off);
    if (lane == 0) out[(size_t)t * 5 + j] = v + b_out[j];
}

extern "C" void kernel_launch(void* const* d_in, const int* in_sizes, int n_in,
                              void* d_out, int out_size) {
    (void)in_sizes; (void)n_in; (void)out_size;
    const float* observed = (const float*)d_in[0];
    const float* other    = (const float*)d_in[1];
    const float* W_emb    = (const float*)d_in[2];
    const float* b_emb    = (const float*)d_in[3];
    const float* W_ih     = (const float*)d_in[4];
    const float* b_ih     = (const float*)d_in[5];
    const float* W_hh     = (const float*)d_in[6];
    const float* b_hh     = (const float*)d_in[7];
    const float* W_out    = (const float*)d_in[8];
    const float* b_out    = (const float*)d_in[9];
    float* out = (float*)d_out;

    olstm_pre<<<P1, TPB>>>(observed, other, W_emb, b_emb, W_ih);
    olstm_seq<<<CS, TPB>>>(observed, other, W_emb, b_emb, W_ih, b_ih,
                           W_hh, b_hh, W_out, b_out, out);
    olstm_head<<<STEPS, 160>>>(W_out, b_out, out);
}